// round 5
// baseline (speedup 1.0000x reference)
#include <cuda_runtime.h>
#include <cstdint>

// Problem constants
constexpr int BB = 256;     // batch
constexpr int H  = 1024;    // hidden
constexpr int L  = 10000;   // labels
constexpr int MT = 128;     // M per CTA
constexpr int LPB = 8;      // labels per CTA (N = 64)
constexpr int KCB = 128;    // K per chunk (int8 => 128B rows)
constexpr int NCHUNK = H / KCB;  // 8

constexpr float SA = 4096.0f;      // emb scale 2^12
constexpr float SB = 131072.0f;    // W1 scale 2^17

// smem buffer layout (per buffer)
constexpr int OFF_AH = 0;          // 128 x 128B = 16KB
constexpr int OFF_AL = 16384;
constexpr int OFF_BH = 32768;      // 64 x 128B  =  8KB
constexpr int OFF_BL = 40960;
constexpr int BUF_BYTES = 49152;
constexpr int SMEM_DYN = 1024 + 2 * BUF_BYTES;  // 99328

// pre-quantized embeddings: int8 hi/lo planes, [256][1024] k-contiguous
__device__ __align__(16) char g_eAh[BB * H];
__device__ __align__(16) char g_eAl[BB * H];

// ---------------- helpers ----------------
__device__ __forceinline__ uint32_t smem_u32(const void* p) {
    uint32_t a;
    asm("{ .reg .u64 t; cvta.to.shared.u64 t, %1; cvt.u32.u64 %0, t; }" : "=r"(a) : "l"(p));
    return a;
}
__device__ __forceinline__ void cpasync16(uint32_t dst, const void* src) {
    asm volatile("cp.async.cg.shared.global [%0], [%1], 16;" :: "r"(dst), "l"(src));
}
#define CP_COMMIT() asm volatile("cp.async.commit_group;" ::: "memory")
#define CP_WAIT0()  asm volatile("cp.async.wait_group 0;" ::: "memory")

__device__ __forceinline__ void ldsm4(uint32_t* r, uint32_t addr) {
    asm volatile("ldmatrix.sync.aligned.m8n8.x4.shared.b16 {%0,%1,%2,%3}, [%4];"
                 : "=r"(r[0]), "=r"(r[1]), "=r"(r[2]), "=r"(r[3]) : "r"(addr));
}
__device__ __forceinline__ void imma(int* c, const uint32_t* a, const uint32_t* b) {
    asm volatile(
        "mma.sync.aligned.m16n8k32.row.col.s32.s8.s8.s32 "
        "{%0,%1,%2,%3}, {%4,%5,%6,%7}, {%8,%9}, {%0,%1,%2,%3};"
        : "+r"(c[0]), "+r"(c[1]), "+r"(c[2]), "+r"(c[3])
        : "r"(a[0]), "r"(a[1]), "r"(a[2]), "r"(a[3]), "r"(b[0]), "r"(b[1]));
}
// quantize x*scale to int16 (clamped), split into hi/lo int8 (both in [-128,127])
__device__ __forceinline__ void quant(float x, float scale, int& ah, int& al) {
    float xs = fminf(fmaxf(x * scale, -32640.0f), 32639.0f);
    int q = __float2int_rn(xs);
    ah = (q + 128) >> 8;
    al = q - (ah << 8);
}
__device__ __forceinline__ uint32_t pk4(int b0, int b1, int b2, int b3) {
    return (uint32_t)(b0 & 0xff) | ((uint32_t)(b1 & 0xff) << 8)
         | ((uint32_t)(b2 & 0xff) << 16) | ((uint32_t)b3 << 24);
}

// ---------------- pre-kernel: emb fp32 -> int8 hi/lo planes ----------------
__global__ void quant_emb_kernel(const float* __restrict__ emb) {
    int i = blockIdx.x * blockDim.x + threadIdx.x;   // 65536 quads
    float4 v = reinterpret_cast<const float4*>(emb)[i];
    int h0, l0, h1, l1, h2, l2, h3, l3;
    quant(v.x, SA, h0, l0);
    quant(v.y, SA, h1, l1);
    quant(v.z, SA, h2, l2);
    quant(v.w, SA, h3, l3);
    reinterpret_cast<uint32_t*>(g_eAh)[i] = pk4(h0, h1, h2, h3);
    reinterpret_cast<uint32_t*>(g_eAl)[i] = pk4(l0, l1, l2, l3);
}

// ---------------- main kernel ----------------
__global__ __launch_bounds__(256, 1)
void imec_imma_kernel(const float* __restrict__ W1,
                      const float* __restrict__ b1,
                      const float* __restrict__ W2,
                      const float* __restrict__ b2,
                      float* __restrict__ out)
{
    extern __shared__ char smraw[];
    uint32_t sraw = smem_u32(smraw);
    uint32_t sb = (sraw + 1023u) & ~1023u;
    char* smc = smraw + (sb - sraw);

    const int tid  = threadIdx.x;
    const int lane = tid & 31;
    const int wid  = tid >> 5;
    const int wm   = wid & 3;      // warp M row (32 rows)
    const int wn   = wid >> 2;     // warp N col (32 cols = 4 labels)

    const int lg = blockIdx.x >> 1;
    const int mt = blockIdx.x & 1;
    const int m0 = mt * MT;
    const int l0 = lg * LPB;

    // ---- A staging (cp.async): thread -> (row, k-half of 64B) ----
    const int ar = tid >> 1;
    const int ahalf = tid & 1;

    // ---- B staging: warp = label, lane = 4-k slice ----
    const int lt = wid;            // label 0..7
    const int sq = lane;           // k-quad 0..31

    // ---- ldmatrix per-lane invariants (byte offsets, 128B rows) ----
    uint32_t aRow[2], aXor[2];
#pragma unroll
    for (int mi = 0; mi < 2; ++mi) {
        int r = wm * 32 + mi * 16 + (lane & 15);
        aRow[mi] = (uint32_t)r * 128u;
        aXor[mi] = (uint32_t)(r & 7) << 4;
    }
    const uint32_t aKadd = (uint32_t)(lane >> 4) << 4;

    uint32_t bRow[2], bXor[2];
#pragma unroll
    for (int nb = 0; nb < 2; ++nb) {
        int r = wn * 32 + nb * 16 + ((lane >> 4) << 3) + (lane & 7);
        bRow[nb] = (uint32_t)r * 128u;
        bXor[nb] = (uint32_t)(r & 7) << 4;
    }
    const uint32_t bKadd = (uint32_t)((lane >> 3) & 1) << 4;

    // s32 accumulators: hh, mid(=hl+lh), ll
    int acc_hh[2][4][4], acc_mid[2][4][4], acc_ll[2][4][4];
#pragma unroll
    for (int mi = 0; mi < 2; ++mi)
#pragma unroll
        for (int ni = 0; ni < 4; ++ni)
#pragma unroll
            for (int k = 0; k < 4; ++k) {
                acc_hh[mi][ni][k] = 0;
                acc_mid[mi][ni][k] = 0;
                acc_ll[mi][ni][k] = 0;
            }

    float4 bv[8];   // W1 prefetch: 4 k x 8 d fp32

    auto stageA = [&](int c, int p) {
        char* buf = smc + p * BUF_BYTES;
        const size_t gofs = (size_t)(m0 + ar) * H + (size_t)c * KCB + ahalf * 64;
#pragma unroll
        for (int j = 0; j < 4; ++j) {
            uint32_t u = (uint32_t)(ahalf * 4 + j);
            uint32_t off = (uint32_t)ar * 128u + ((u ^ (uint32_t)(ar & 7)) << 4);
            cpasync16(sb + (uint32_t)(p * BUF_BYTES) + OFF_AH + off, g_eAh + gofs + j * 16);
            cpasync16(sb + (uint32_t)(p * BUF_BYTES) + OFF_AL + off, g_eAl + gofs + j * 16);
        }
        (void)buf;
    };

    auto ldgB = [&](int c) {
        const float4* bsrc = reinterpret_cast<const float4*>(
            W1 + (size_t)(l0 + lt) * (H * 8) + ((size_t)c * KCB + sq * 4) * 8);
#pragma unroll
        for (int j = 0; j < 8; ++j) bv[j] = bsrc[j];
    };

    auto stsB = [&](int p) {
        char* buf = smc + p * BUF_BYTES;
        const float* fp = reinterpret_cast<const float*>(bv);   // fp[k*8+d], k=0..3
#pragma unroll
        for (int d = 0; d < 8; ++d) {
            int h0, l0v, h1, l1v, h2, l2v, h3, l3v;
            quant(fp[0 + d],  SB, h0, l0v);
            quant(fp[8 + d],  SB, h1, l1v);
            quant(fp[16 + d], SB, h2, l2v);
            quant(fp[24 + d], SB, h3, l3v);
            int n = lt * 8 + d;
            uint32_t off = (uint32_t)n * 128u
                         + ((((uint32_t)(sq >> 2)) ^ (uint32_t)(n & 7)) << 4)
                         + (uint32_t)(sq & 3) * 4u;
            *reinterpret_cast<uint32_t*>(buf + OFF_BH + off) = pk4(h0, h1, h2, h3);
            *reinterpret_cast<uint32_t*>(buf + OFF_BL + off) = pk4(l0v, l1v, l2v, l3v);
        }
    };

    auto compute = [&](int p) {
        const uint32_t base = sb + (uint32_t)p * BUF_BYTES;
        const uint32_t bAH = base + OFF_AH, bAL = base + OFF_AL;
        const uint32_t bBH = base + OFF_BH, bBL = base + OFF_BL;
#pragma unroll
        for (int ks = 0; ks < 4; ++ks) {
            const uint32_t koff = (uint32_t)ks * 32u;
            uint32_t a_h[2][4], a_l[2][4], b_h[2][4], b_l[2][4];
#pragma unroll
            for (int mi = 0; mi < 2; ++mi) {
                ldsm4(a_h[mi], bAH + aRow[mi] + ((koff + aKadd) ^ aXor[mi]));
                ldsm4(a_l[mi], bAL + aRow[mi] + ((koff + aKadd) ^ aXor[mi]));
            }
#pragma unroll
            for (int nb = 0; nb < 2; ++nb) {
                ldsm4(b_h[nb], bBH + bRow[nb] + ((koff + bKadd) ^ bXor[nb]));
                ldsm4(b_l[nb], bBL + bRow[nb] + ((koff + bKadd) ^ bXor[nb]));
            }
#pragma unroll
            for (int mi = 0; mi < 2; ++mi)
#pragma unroll
                for (int ni = 0; ni < 4; ++ni) {
                    const uint32_t* bh = &b_h[ni >> 1][(ni & 1) * 2];
                    const uint32_t* bl = &b_l[ni >> 1][(ni & 1) * 2];
                    imma(acc_hh[mi][ni],  a_h[mi], bh);
                    imma(acc_mid[mi][ni], a_h[mi], bl);
                    imma(acc_mid[mi][ni], a_l[mi], bh);
                    imma(acc_ll[mi][ni],  a_l[mi], bl);
                }
        }
    };

    // ---- software pipeline ----
    stageA(0, 0);
    CP_COMMIT();
    ldgB(0);
    stsB(0);
    CP_WAIT0();
    __syncthreads();

    for (int c = 0; c < NCHUNK; ++c) {
        const int p = c & 1;
        if (c + 1 < NCHUNK) {
            stageA(c + 1, p ^ 1);
            CP_COMMIT();
            ldgB(c + 1);
        }
        compute(p);
        if (c + 1 < NCHUNK) {
            stsB(p ^ 1);
            CP_WAIT0();
        }
        __syncthreads();
    }

    // ---- epilogue: h = (hh*2^16 + mid*2^8 + ll)/(SA*SB); relu(h+b1).W2 + b2 ----
    const int gid = lane >> 2;
    const int tq  = lane & 3;
#pragma unroll
    for (int ni = 0; ni < 4; ++ni) {
        const int l = l0 + wn * 4 + ni;
        float2 bbv = *reinterpret_cast<const float2*>(b1 + (size_t)l * 8 + tq * 2);
        float2 wwv = *reinterpret_cast<const float2*>(W2 + (size_t)l * 8 + tq * 2);
        const float b2v = __ldg(b2 + l);
#pragma unroll
        for (int mi = 0; mi < 2; ++mi) {
            float hv[4];
#pragma unroll
            for (int k = 0; k < 4; ++k) {
                hv[k] = (float)acc_hh[mi][ni][k] * 0x1p-13f
                      + (float)acc_mid[mi][ni][k] * 0x1p-21f
                      + (float)acc_ll[mi][ni][k] * 0x1p-29f;
            }
            float s0 = fmaxf(hv[0] + bbv.x, 0.0f) * wwv.x
                     + fmaxf(hv[1] + bbv.y, 0.0f) * wwv.y;
            float s1 = fmaxf(hv[2] + bbv.x, 0.0f) * wwv.x
                     + fmaxf(hv[3] + bbv.y, 0.0f) * wwv.y;
            s0 += __shfl_xor_sync(0xffffffffu, s0, 1);
            s0 += __shfl_xor_sync(0xffffffffu, s0, 2);
            s1 += __shfl_xor_sync(0xffffffffu, s1, 1);
            s1 += __shfl_xor_sync(0xffffffffu, s1, 2);
            if (tq == 0) {
                const int b = m0 + wm * 32 + mi * 16 + gid;
                out[(size_t)b * L + l]       = s0 + b2v;
                out[(size_t)(b + 8) * L + l] = s1 + b2v;
            }
        }
    }
}

extern "C" void kernel_launch(void* const* d_in, const int* in_sizes, int n_in,
                              void* d_out, int out_size)
{
    const float* emb = (const float*)d_in[0];  // [B, H]
    const float* W1  = (const float*)d_in[1];  // [L, H, 8]
    const float* b1  = (const float*)d_in[2];  // [L, 8]
    const float* W2  = (const float*)d_in[3];  // [L, 8]
    const float* b2  = (const float*)d_in[4];  // [L]
    float* out       = (float*)d_out;          // [B, L]

    cudaFuncSetAttribute(imec_imma_kernel,
                         cudaFuncAttributeMaxDynamicSharedMemorySize, SMEM_DYN);

    quant_emb_kernel<<<BB * H / 4 / 256, 256>>>(emb);
    imec_imma_kernel<<<(L / LPB) * 2, 256, SMEM_DYN>>>(W1, b1, W2, b2, out);
}

// round 6
// speedup vs baseline: 4.8671x; 4.8671x over previous
#include <cuda_runtime.h>
#include <cuda_fp16.h>
#include <cstdint>

// Problem constants
constexpr int BB = 256;     // batch
constexpr int H  = 1024;    // hidden
constexpr int L  = 10000;   // labels
constexpr int MT = 128;     // M per CTA
constexpr int LPB = 16;     // labels per CTA (N = 128)
constexpr int KC = 64;      // K per chunk (fp16 => 128B rows)
constexpr int NCHUNK = H / KC;  // 16

// smem per buffer: A 128x128B = 16KB, B 128x128B = 16KB
constexpr int OFF_A = 0;
constexpr int OFF_B = 16384;
constexpr int BUF_BYTES = 32768;
constexpr int SMEM_DYN = 1024 + 2 * BUF_BYTES;   // 66560

// pre-converted embeddings (fp16), [256][1024] k-contiguous
__device__ __align__(16) __half g_eA[BB * H];

// ---------------- helpers ----------------
__device__ __forceinline__ uint32_t smem_u32(const void* p) {
    uint32_t a;
    asm("{ .reg .u64 t; cvta.to.shared.u64 t, %1; cvt.u32.u64 %0, t; }" : "=r"(a) : "l"(p));
    return a;
}
__device__ __forceinline__ void cpasync16(uint32_t dst, const void* src) {
    asm volatile("cp.async.cg.shared.global [%0], [%1], 16;" :: "r"(dst), "l"(src));
}
#define CP_COMMIT() asm volatile("cp.async.commit_group;" ::: "memory")
#define CP_WAIT0()  asm volatile("cp.async.wait_group 0;" ::: "memory")

__device__ __forceinline__ void ldsm4(uint32_t* r, uint32_t addr) {
    asm volatile("ldmatrix.sync.aligned.m8n8.x4.shared.b16 {%0,%1,%2,%3}, [%4];"
                 : "=r"(r[0]), "=r"(r[1]), "=r"(r[2]), "=r"(r[3]) : "r"(addr));
}
__device__ __forceinline__ void mma16816(float* c, const uint32_t* a, const uint32_t* b) {
    asm volatile(
        "mma.sync.aligned.m16n8k16.row.col.f32.f16.f16.f32 "
        "{%0,%1,%2,%3}, {%4,%5,%6,%7}, {%8,%9}, {%0,%1,%2,%3};"
        : "+f"(c[0]), "+f"(c[1]), "+f"(c[2]), "+f"(c[3])
        : "r"(a[0]), "r"(a[1]), "r"(a[2]), "r"(a[3]), "r"(b[0]), "r"(b[1]));
}
__device__ __forceinline__ uint32_t pkh2(float x0, float x1) {
    __half2 h = __float22half2_rn(make_float2(x0, x1));
    return *reinterpret_cast<uint32_t*>(&h);
}

// ---------------- pre-kernel: emb fp32 -> fp16 ----------------
__global__ void cvt_emb_kernel(const float* __restrict__ emb) {
    int i = blockIdx.x * blockDim.x + threadIdx.x;   // 65536 float4s
    float4 v = reinterpret_cast<const float4*>(emb)[i];
    reinterpret_cast<uint2*>(g_eA)[i] = make_uint2(pkh2(v.x, v.y), pkh2(v.z, v.w));
}

// ---------------- main kernel ----------------
__global__ __launch_bounds__(256, 2)
void imec_hmma_kernel(const float* __restrict__ W1,
                      const float* __restrict__ b1,
                      const float* __restrict__ W2,
                      const float* __restrict__ b2,
                      float* __restrict__ out)
{
    extern __shared__ char smraw[];
    uint32_t sraw = smem_u32(smraw);
    uint32_t sb = (sraw + 1023u) & ~1023u;
    char* smc = smraw + (sb - sraw);

    const int tid  = threadIdx.x;
    const int lane = tid & 31;
    const int wid  = tid >> 5;
    const int wm   = wid & 3;      // warp M row (32 rows)
    const int wn   = wid >> 2;     // warp N col (64 cols)

    const int lg = blockIdx.x >> 1;
    const int mt = blockIdx.x & 1;
    const int m0 = mt * MT;
    const int l0 = lg * LPB;

    // A staging (cp.async): thread -> (row, k-half)
    const int ar = tid >> 1;
    const int ahalf = tid & 1;

    // B staging: thread -> (label, k-quad)
    const int lt = tid >> 4;       // 0..15
    const int sq = tid & 15;       // covers k = sq*4 .. sq*4+3

    // ldmatrix per-lane invariants (byte offsets, 128B rows) — same as R4
    uint32_t aRow[2], aXor[2];
#pragma unroll
    for (int mi = 0; mi < 2; ++mi) {
        int r = wm * 32 + mi * 16 + (lane & 15);
        aRow[mi] = (uint32_t)r * 128u;
        aXor[mi] = (uint32_t)(r & 7) << 4;
    }
    const uint32_t aKadd = (uint32_t)(lane >> 4) << 4;

    uint32_t bRow[4], bXor[4];
#pragma unroll
    for (int nb = 0; nb < 4; ++nb) {
        int r = wn * 64 + nb * 16 + ((lane >> 4) << 3) + (lane & 7);
        bRow[nb] = (uint32_t)r * 128u;
        bXor[nb] = (uint32_t)(r & 7) << 4;
    }
    const uint32_t bKadd = (uint32_t)((lane >> 3) & 1) << 4;

    float acc[2][8][4];
#pragma unroll
    for (int mi = 0; mi < 2; ++mi)
#pragma unroll
        for (int ni = 0; ni < 8; ++ni)
#pragma unroll
            for (int k = 0; k < 4; ++k) acc[mi][ni][k] = 0.0f;

    auto stageA = [&](int c, int p) {
        const char* src = reinterpret_cast<const char*>(g_eA)
                        + (size_t)(m0 + ar) * (H * 2) + (size_t)c * (KC * 2) + ahalf * 64;
        const uint32_t dbase = sb + (uint32_t)(p * BUF_BYTES) + OFF_A + (uint32_t)ar * 128u;
#pragma unroll
        for (int j = 0; j < 4; ++j) {
            uint32_t u = (uint32_t)(ahalf * 4 + j);
            cpasync16(dbase + ((u ^ (uint32_t)(ar & 7)) << 4), src + j * 16);
        }
    };

    auto loadStoreB = [&](int c, int p) {
        const float4* bsrc = reinterpret_cast<const float4*>(
            W1 + (size_t)(l0 + lt) * (H * 8) + ((size_t)c * KC + sq * 4) * 8);
        float4 bv[8];
#pragma unroll
        for (int j = 0; j < 8; ++j) bv[j] = bsrc[j];
        char* buf = smc + p * BUF_BYTES + OFF_B;
        const float* fp = reinterpret_cast<const float*>(bv);   // fp[k*8+d], k=0..3
#pragma unroll
        for (int d = 0; d < 8; ++d) {
            uint32_t w01 = pkh2(fp[0 + d],  fp[8 + d]);
            uint32_t w23 = pkh2(fp[16 + d], fp[24 + d]);
            int n = lt * 8 + d;
            uint32_t off = (uint32_t)n * 128u + (((uint32_t)(sq * 8)) ^ ((uint32_t)(n & 7) << 4));
            *reinterpret_cast<uint2*>(buf + off) = make_uint2(w01, w23);
        }
    };

    auto compute = [&](int p) {
        const uint32_t base = sb + (uint32_t)p * BUF_BYTES;
        const uint32_t bA = base + OFF_A, bB = base + OFF_B;
#pragma unroll
        for (int ks = 0; ks < 4; ++ks) {
            const uint32_t koff = (uint32_t)ks * 32u;
            uint32_t a[2][4], b[4][4];
#pragma unroll
            for (int mi = 0; mi < 2; ++mi)
                ldsm4(a[mi], bA + aRow[mi] + ((koff + aKadd) ^ aXor[mi]));
#pragma unroll
            for (int nb = 0; nb < 4; ++nb)
                ldsm4(b[nb], bB + bRow[nb] + ((koff + bKadd) ^ bXor[nb]));
#pragma unroll
            for (int mi = 0; mi < 2; ++mi)
#pragma unroll
                for (int ni = 0; ni < 8; ++ni)
                    mma16816(acc[mi][ni], a[mi], &b[ni >> 1][(ni & 1) * 2]);
        }
    };

    // ---- software pipeline (double buffer) ----
    stageA(0, 0);
    CP_COMMIT();
    loadStoreB(0, 0);
    CP_WAIT0();
    __syncthreads();

    for (int c = 0; c < NCHUNK; ++c) {
        const int p = c & 1;
        if (c + 1 < NCHUNK) {
            stageA(c + 1, p ^ 1);
            CP_COMMIT();
        }
        compute(p);
        if (c + 1 < NCHUNK) {
            loadStoreB(c + 1, p ^ 1);
            CP_WAIT0();
        }
        __syncthreads();
    }

    // ---- epilogue: relu(h + b1) . W2 + b2, quad-reduce over d ----
    const int gid = lane >> 2;
    const int tq  = lane & 3;
#pragma unroll
    for (int ni = 0; ni < 8; ++ni) {
        const int l = l0 + wn * 8 + ni;
        float2 bbv = *reinterpret_cast<const float2*>(b1 + (size_t)l * 8 + tq * 2);
        float2 wwv = *reinterpret_cast<const float2*>(W2 + (size_t)l * 8 + tq * 2);
        const float b2v = __ldg(b2 + l);
#pragma unroll
        for (int mi = 0; mi < 2; ++mi) {
            float s0 = fmaxf(acc[mi][ni][0] + bbv.x, 0.0f) * wwv.x
                     + fmaxf(acc[mi][ni][1] + bbv.y, 0.0f) * wwv.y;
            float s1 = fmaxf(acc[mi][ni][2] + bbv.x, 0.0f) * wwv.x
                     + fmaxf(acc[mi][ni][3] + bbv.y, 0.0f) * wwv.y;
            s0 += __shfl_xor_sync(0xffffffffu, s0, 1);
            s0 += __shfl_xor_sync(0xffffffffu, s0, 2);
            s1 += __shfl_xor_sync(0xffffffffu, s1, 1);
            s1 += __shfl_xor_sync(0xffffffffu, s1, 2);
            if (tq == 0) {
                const int b = m0 + wm * 32 + mi * 16 + gid;
                out[(size_t)b * L + l]       = s0 + b2v;
                out[(size_t)(b + 8) * L + l] = s1 + b2v;
            }
        }
    }
}

extern "C" void kernel_launch(void* const* d_in, const int* in_sizes, int n_in,
                              void* d_out, int out_size)
{
    const float* emb = (const float*)d_in[0];  // [B, H]
    const float* W1  = (const float*)d_in[1];  // [L, H, 8]
    const float* b1  = (const float*)d_in[2];  // [L, 8]
    const float* W2  = (const float*)d_in[3];  // [L, 8]
    const float* b2  = (const float*)d_in[4];  // [L]
    float* out       = (float*)d_out;          // [B, L]

    cudaFuncSetAttribute(imec_hmma_kernel,
                         cudaFuncAttributeMaxDynamicSharedMemorySize, SMEM_DYN);

    cvt_emb_kernel<<<BB * H / 4 / 256, 256>>>(emb);
    imec_hmma_kernel<<<(L / LPB) * 2, 256, SMEM_DYN>>>(W1, b1, W2, b2, out);
}

// round 7
// speedup vs baseline: 5.1394x; 1.0559x over previous
#include <cuda_runtime.h>
#include <cuda_fp16.h>
#include <cstdint>

// Problem constants
constexpr int BB = 256;     // batch (= M per CTA, full batch)
constexpr int H  = 1024;    // hidden
constexpr int L  = 10000;   // labels
constexpr int LPB = 16;     // labels per CTA (N = 128)
constexpr int KC = 64;      // K per chunk (fp16 => 128B rows)
constexpr int NCHUNK = H / KC;  // 16

// smem per buffer: A 256x128B = 32KB, B 128x128B = 16KB
constexpr int OFF_A = 0;
constexpr int OFF_B = 32768;
constexpr int BUF_BYTES = 49152;
constexpr int SMEM_DYN = 1024 + 2 * BUF_BYTES;   // 99328

// pre-converted embeddings (fp16), [256][1024] k-contiguous
__device__ __align__(16) __half g_eA[BB * H];

// ---------------- helpers ----------------
__device__ __forceinline__ uint32_t smem_u32(const void* p) {
    uint32_t a;
    asm("{ .reg .u64 t; cvta.to.shared.u64 t, %1; cvt.u32.u64 %0, t; }" : "=r"(a) : "l"(p));
    return a;
}
__device__ __forceinline__ void cpasync16(uint32_t dst, const void* src) {
    asm volatile("cp.async.cg.shared.global [%0], [%1], 16;" :: "r"(dst), "l"(src));
}
#define CP_COMMIT() asm volatile("cp.async.commit_group;" ::: "memory")
#define CP_WAIT0()  asm volatile("cp.async.wait_group 0;" ::: "memory")

__device__ __forceinline__ void ldsm4(uint32_t* r, uint32_t addr) {
    asm volatile("ldmatrix.sync.aligned.m8n8.x4.shared.b16 {%0,%1,%2,%3}, [%4];"
                 : "=r"(r[0]), "=r"(r[1]), "=r"(r[2]), "=r"(r[3]) : "r"(addr));
}
__device__ __forceinline__ void mma16816(float* c, const uint32_t* a, const uint32_t* b) {
    asm volatile(
        "mma.sync.aligned.m16n8k16.row.col.f32.f16.f16.f32 "
        "{%0,%1,%2,%3}, {%4,%5,%6,%7}, {%8,%9}, {%0,%1,%2,%3};"
        : "+f"(c[0]), "+f"(c[1]), "+f"(c[2]), "+f"(c[3])
        : "r"(a[0]), "r"(a[1]), "r"(a[2]), "r"(a[3]), "r"(b[0]), "r"(b[1]));
}
__device__ __forceinline__ uint32_t pkh2(float x0, float x1) {
    __half2 h = __float22half2_rn(make_float2(x0, x1));
    return *reinterpret_cast<uint32_t*>(&h);
}

// ---------------- pre-kernel: emb fp32 -> fp16 ----------------
__global__ void cvt_emb_kernel(const float* __restrict__ emb) {
    int i = blockIdx.x * blockDim.x + threadIdx.x;   // 65536 float4s
    float4 v = reinterpret_cast<const float4*>(emb)[i];
    reinterpret_cast<uint2*>(g_eA)[i] = make_uint2(pkh2(v.x, v.y), pkh2(v.z, v.w));
}

// ---------------- main kernel ----------------
__global__ __launch_bounds__(256, 1)
void imec_hmma_kernel(const float* __restrict__ W1,
                      const float* __restrict__ b1,
                      const float* __restrict__ W2,
                      const float* __restrict__ b2,
                      float* __restrict__ out)
{
    extern __shared__ char smraw[];
    uint32_t sraw = smem_u32(smraw);
    uint32_t sb = (sraw + 1023u) & ~1023u;
    char* smc = smraw + (sb - sraw);

    const int tid  = threadIdx.x;
    const int lane = tid & 31;
    const int wid  = tid >> 5;
    const int wm   = wid & 3;      // warp M row (64 rows each, 4 x 64 = 256)
    const int wn   = wid >> 2;     // warp N col (64 cols each, 2 x 64 = 128)

    const int l0 = blockIdx.x * LPB;

    // A staging (cp.async): one thread per row, 8 x 16B units
    const int ar = tid;            // 0..255

    // B staging: thread -> (label, k-quad)
    const int lt = tid >> 4;       // label 0..15
    const int sq = tid & 15;       // covers k = sq*4 .. sq*4+3

    // ldmatrix per-lane invariants (byte offsets, 128B rows)
    uint32_t aRow[4], aXor[4];
#pragma unroll
    for (int mi = 0; mi < 4; ++mi) {
        int r = wm * 64 + mi * 16 + (lane & 15);
        aRow[mi] = (uint32_t)r * 128u;
        aXor[mi] = (uint32_t)(r & 7) << 4;
    }
    const uint32_t aKadd = (uint32_t)(lane >> 4) << 4;

    uint32_t bRow[4], bXor[4];
#pragma unroll
    for (int nb = 0; nb < 4; ++nb) {
        int r = wn * 64 + nb * 16 + ((lane >> 4) << 3) + (lane & 7);
        bRow[nb] = (uint32_t)r * 128u;
        bXor[nb] = (uint32_t)(r & 7) << 4;
    }
    const uint32_t bKadd = (uint32_t)((lane >> 3) & 1) << 4;

    float acc[4][8][4];
#pragma unroll
    for (int mi = 0; mi < 4; ++mi)
#pragma unroll
        for (int ni = 0; ni < 8; ++ni)
#pragma unroll
            for (int k = 0; k < 4; ++k) acc[mi][ni][k] = 0.0f;

    float4 bv[8];   // W1 prefetch registers (4 k x 8 d fp32)

    auto stageA = [&](int c, int p) {
        const char* src = reinterpret_cast<const char*>(g_eA)
                        + (size_t)ar * (H * 2) + (size_t)c * (KC * 2);
        const uint32_t dbase = sb + (uint32_t)(p * BUF_BYTES) + OFF_A + (uint32_t)ar * 128u;
        const uint32_t rx = (uint32_t)(ar & 7);
#pragma unroll
        for (int u = 0; u < 8; ++u)
            cpasync16(dbase + (((uint32_t)u ^ rx) << 4), src + u * 16);
    };

    auto ldgB = [&](int c) {
        const float4* bsrc = reinterpret_cast<const float4*>(
            W1 + (size_t)(l0 + lt) * (H * 8) + ((size_t)c * KC + sq * 4) * 8);
#pragma unroll
        for (int j = 0; j < 8; ++j) bv[j] = bsrc[j];
    };

    auto stsB = [&](int p) {
        char* buf = smc + p * BUF_BYTES + OFF_B;
        const float* fp = reinterpret_cast<const float*>(bv);   // fp[k*8+d], k=0..3
#pragma unroll
        for (int d = 0; d < 8; ++d) {
            uint32_t w01 = pkh2(fp[0 + d],  fp[8 + d]);
            uint32_t w23 = pkh2(fp[16 + d], fp[24 + d]);
            int n = lt * 8 + d;
            uint32_t off = (uint32_t)n * 128u + (((uint32_t)(sq * 8)) ^ ((uint32_t)(n & 7) << 4));
            *reinterpret_cast<uint2*>(buf + off) = make_uint2(w01, w23);
        }
    };

    auto compute = [&](int p) {
        const uint32_t base = sb + (uint32_t)p * BUF_BYTES;
        const uint32_t bA = base + OFF_A, bB = base + OFF_B;
#pragma unroll
        for (int ks = 0; ks < 4; ++ks) {
            const uint32_t koff = (uint32_t)ks * 32u;
            uint32_t a[4][4], b[4][4];
#pragma unroll
            for (int mi = 0; mi < 4; ++mi)
                ldsm4(a[mi], bA + aRow[mi] + ((koff + aKadd) ^ aXor[mi]));
#pragma unroll
            for (int nb = 0; nb < 4; ++nb)
                ldsm4(b[nb], bB + bRow[nb] + ((koff + bKadd) ^ bXor[nb]));
#pragma unroll
            for (int mi = 0; mi < 4; ++mi)
#pragma unroll
                for (int ni = 0; ni < 8; ++ni)
                    mma16816(acc[mi][ni], a[mi], &b[ni >> 1][(ni & 1) * 2]);
        }
    };

    // ---- software pipeline (double buffer, LDG prefetch before compute) ----
    stageA(0, 0);
    CP_COMMIT();
    ldgB(0);
    stsB(0);
    CP_WAIT0();
    __syncthreads();

    for (int c = 0; c < NCHUNK; ++c) {
        const int p = c & 1;
        if (c + 1 < NCHUNK) {
            stageA(c + 1, p ^ 1);
            CP_COMMIT();
            ldgB(c + 1);         // LDG issued BEFORE compute: latency hidden
        }
        compute(p);
        if (c + 1 < NCHUNK) {
            stsB(p ^ 1);
            CP_WAIT0();
        }
        __syncthreads();
    }

    // ---- epilogue: relu(h + b1) . W2 + b2, quad-reduce over d ----
    const int gid = lane >> 2;
    const int tq  = lane & 3;
#pragma unroll
    for (int ni = 0; ni < 8; ++ni) {
        const int l = l0 + wn * 8 + ni;
        float2 bbv = *reinterpret_cast<const float2*>(b1 + (size_t)l * 8 + tq * 2);
        float2 wwv = *reinterpret_cast<const float2*>(W2 + (size_t)l * 8 + tq * 2);
        const float b2v = __ldg(b2 + l);
#pragma unroll
        for (int mi = 0; mi < 4; ++mi) {
            float s0 = fmaxf(acc[mi][ni][0] + bbv.x, 0.0f) * wwv.x
                     + fmaxf(acc[mi][ni][1] + bbv.y, 0.0f) * wwv.y;
            float s1 = fmaxf(acc[mi][ni][2] + bbv.x, 0.0f) * wwv.x
                     + fmaxf(acc[mi][ni][3] + bbv.y, 0.0f) * wwv.y;
            s0 += __shfl_xor_sync(0xffffffffu, s0, 1);
            s0 += __shfl_xor_sync(0xffffffffu, s0, 2);
            s1 += __shfl_xor_sync(0xffffffffu, s1, 1);
            s1 += __shfl_xor_sync(0xffffffffu, s1, 2);
            if (tq == 0) {
                const int b = wm * 64 + mi * 16 + gid;
                out[(size_t)b * L + l]       = s0 + b2v;
                out[(size_t)(b + 8) * L + l] = s1 + b2v;
            }
        }
    }
}

extern "C" void kernel_launch(void* const* d_in, const int* in_sizes, int n_in,
                              void* d_out, int out_size)
{
    const float* emb = (const float*)d_in[0];  // [B, H]
    const float* W1  = (const float*)d_in[1];  // [L, H, 8]
    const float* b1  = (const float*)d_in[2];  // [L, 8]
    const float* W2  = (const float*)d_in[3];  // [L, 8]
    const float* b2  = (const float*)d_in[4];  // [L]
    float* out       = (float*)d_out;          // [B, L]

    cudaFuncSetAttribute(imec_hmma_kernel,
                         cudaFuncAttributeMaxDynamicSharedMemorySize, SMEM_DYN);

    cvt_emb_kernel<<<BB * H / 4 / 256, 256>>>(emb);
    imec_hmma_kernel<<<L / LPB, 256, SMEM_DYN>>>(W1, b1, W2, b2, out);
}

// round 8
// speedup vs baseline: 6.4853x; 1.2619x over previous
#include <cuda_runtime.h>
#include <cuda_fp16.h>
#include <cstdint>

// Problem constants
constexpr int BB = 256;     // batch
constexpr int H  = 1024;    // hidden
constexpr int L  = 10000;   // labels
constexpr int MT = 128;     // M per CTA
constexpr int LPB = 16;     // labels per CTA (N = 128)
constexpr int KC = 64;      // K per chunk
constexpr int NCHUNK = H / KC;  // 16
constexpr int NSTAGE = 3;

// per-stage smem: A 128x128B = 16KB, B 16x1KB = 16KB
constexpr int OFF_A = 0;
constexpr int OFF_B = 16384;
constexpr int STAGE_BYTES = 32768;
constexpr int SMEM_DYN = 1024 + NSTAGE * STAGE_BYTES;   // 99328

// pre-converted fp16 operands
__device__ __align__(16) __half g_eA[BB * H];          // [256][1024]
__device__ __align__(16) __half g_W1h[(size_t)L * H * 8];  // [10000][1024][8], 160MB

// ---------------- helpers ----------------
__device__ __forceinline__ uint32_t smem_u32(const void* p) {
    uint32_t a;
    asm("{ .reg .u64 t; cvta.to.shared.u64 t, %1; cvt.u32.u64 %0, t; }" : "=r"(a) : "l"(p));
    return a;
}
__device__ __forceinline__ void cpasync16(uint32_t dst, const void* src) {
    asm volatile("cp.async.cg.shared.global [%0], [%1], 16;" :: "r"(dst), "l"(src));
}
#define CP_COMMIT() asm volatile("cp.async.commit_group;" ::: "memory")
#define CP_WAIT1()  asm volatile("cp.async.wait_group 1;" ::: "memory")
#define CP_WAIT0()  asm volatile("cp.async.wait_group 0;" ::: "memory")

__device__ __forceinline__ void ldsm4(uint32_t* r, uint32_t addr) {
    asm volatile("ldmatrix.sync.aligned.m8n8.x4.shared.b16 {%0,%1,%2,%3}, [%4];"
                 : "=r"(r[0]), "=r"(r[1]), "=r"(r[2]), "=r"(r[3]) : "r"(addr));
}
__device__ __forceinline__ void ldsm4t(uint32_t* r, uint32_t addr) {
    asm volatile("ldmatrix.sync.aligned.m8n8.x4.trans.shared.b16 {%0,%1,%2,%3}, [%4];"
                 : "=r"(r[0]), "=r"(r[1]), "=r"(r[2]), "=r"(r[3]) : "r"(addr));
}
__device__ __forceinline__ void mma16816(float* c, const uint32_t* a, const uint32_t* b) {
    asm volatile(
        "mma.sync.aligned.m16n8k16.row.col.f32.f16.f16.f32 "
        "{%0,%1,%2,%3}, {%4,%5,%6,%7}, {%8,%9}, {%0,%1,%2,%3};"
        : "+f"(c[0]), "+f"(c[1]), "+f"(c[2]), "+f"(c[3])
        : "r"(a[0]), "r"(a[1]), "r"(a[2]), "r"(a[3]), "r"(b[0]), "r"(b[1]));
}
__device__ __forceinline__ uint32_t pkh2(float x0, float x1) {
    __half2 h = __float22half2_rn(make_float2(x0, x1));
    return *reinterpret_cast<uint32_t*>(&h);
}

// ---------------- pre-kernels ----------------
__global__ void cvt_emb_kernel(const float* __restrict__ emb) {
    int i = blockIdx.x * blockDim.x + threadIdx.x;   // 65536 float4s
    float4 v = reinterpret_cast<const float4*>(emb)[i];
    reinterpret_cast<uint2*>(g_eA)[i] = make_uint2(pkh2(v.x, v.y), pkh2(v.z, v.w));
}
__global__ void cvt_w1_kernel(const float* __restrict__ W1) {
    size_t i = (size_t)blockIdx.x * blockDim.x + threadIdx.x;  // 10,240,000 uint4 outputs
    const float4* s = reinterpret_cast<const float4*>(W1) + 2 * i;
    float4 f0 = s[0], f1 = s[1];
    uint4 o;
    o.x = pkh2(f0.x, f0.y); o.y = pkh2(f0.z, f0.w);
    o.z = pkh2(f1.x, f1.y); o.w = pkh2(f1.z, f1.w);
    reinterpret_cast<uint4*>(g_W1h)[i] = o;
}

// ---------------- main kernel ----------------
__global__ __launch_bounds__(256, 2)
void imec_hmma_kernel(const float* __restrict__ b1,
                      const float* __restrict__ W2,
                      const float* __restrict__ b2,
                      float* __restrict__ out)
{
    extern __shared__ char smraw[];
    uint32_t sraw = smem_u32(smraw);
    uint32_t sb = (sraw + 1023u) & ~1023u;

    const int tid  = threadIdx.x;
    const int lane = tid & 31;
    const int wid  = tid >> 5;
    const int wm   = wid & 1;      // warp M group (64 rows each; 2 x 64 = 128)
    const int wn   = wid >> 1;     // warp N group (32 cols = 4 labels; 4 x 32 = 128)

    const int lg = blockIdx.x >> 1;
    const int mt = blockIdx.x & 1;
    const int m0 = mt * MT;
    const int l0 = lg * LPB;

    // ---- A staging: thread -> (row, k-half), swizzled 128B rows ----
    const int ar = tid >> 1;          // 0..127
    const int ahalf = tid & 1;
    const char* aSrc = reinterpret_cast<const char*>(g_eA)
                     + (size_t)(m0 + ar) * (H * 2) + ahalf * 64;
    const uint32_t aDstBase = (uint32_t)(ar * 128);
    const uint32_t arx = (uint32_t)(ar & 7);

    // ---- B staging: thread -> (label, 16B-unit), verbatim copy ----
    const int lt = tid >> 4;          // 0..15
    const int u0 = tid & 15;
    const char* bSrc = reinterpret_cast<const char*>(g_W1h)
                     + (size_t)(l0 + lt) * (H * 8 * 2);
    const uint32_t bDstBase = (uint32_t)(lt * 1024);

    // ---- A fragment addresses (K-major, swizzled; same as R7) ----
    uint32_t aOff[4], aXor[4];
#pragma unroll
    for (int mi = 0; mi < 4; ++mi) {
        int r = wm * 64 + mi * 16 + (lane & 15);
        aOff[mi] = (uint32_t)r * 128u;
        aXor[mi] = (uint32_t)(r & 7) << 4;
    }
    const uint32_t aKadd = (uint32_t)(lane >> 4) << 4;

    // ---- B fragment addresses (MN-major per-label 1KB blobs, trans ldsm) ----
    // x4.trans i: lanes 0-15 -> label wn*4+2i rows ko..ko+15; lanes 16-31 -> label +1
    uint32_t bOff[2];
#pragma unroll
    for (int i = 0; i < 2; ++i)
        bOff[i] = (uint32_t)((wn * 4 + 2 * i + (lane >> 4)) * 1024 + (lane & 15) * 16);

    float acc[4][4][4];
#pragma unroll
    for (int mi = 0; mi < 4; ++mi)
#pragma unroll
        for (int ni = 0; ni < 4; ++ni)
#pragma unroll
            for (int k = 0; k < 4; ++k) acc[mi][ni][k] = 0.0f;

    auto stage = [&](int c) {
        const int p = c % NSTAGE;
        const uint32_t base = sb + (uint32_t)(p * STAGE_BYTES);
        // A: 4 x 16B
        const char* as = aSrc + c * 128;
        const uint32_t ad = base + OFF_A + aDstBase;
#pragma unroll
        for (int j = 0; j < 4; ++j) {
            uint32_t u = (uint32_t)(ahalf * 4 + j);
            cpasync16(ad + ((u ^ arx) << 4), as + j * 16);
        }
        // B: 4 x 16B (units u0, u0+16, u0+32, u0+48 of this label's 1KB blob)
        const char* bs = bSrc + c * 1024;
        const uint32_t bd = base + OFF_B + bDstBase;
#pragma unroll
        for (int it = 0; it < 4; ++it) {
            uint32_t u = (uint32_t)(u0 + 16 * it);
            cpasync16(bd + u * 16, bs + u * 16);
        }
    };

    auto compute = [&](int c) {
        const int p = c % NSTAGE;
        const uint32_t base = sb + (uint32_t)(p * STAGE_BYTES);
        const uint32_t bA = base + OFF_A, bB = base + OFF_B;
#pragma unroll
        for (int ks = 0; ks < 4; ++ks) {
            const uint32_t koff = (uint32_t)ks * 32u;
            uint32_t a[4][4], b[2][4];
#pragma unroll
            for (int mi = 0; mi < 4; ++mi)
                ldsm4(a[mi], bA + aOff[mi] + ((koff + aKadd) ^ aXor[mi]));
#pragma unroll
            for (int i = 0; i < 2; ++i)
                ldsm4t(b[i], bB + bOff[i] + (uint32_t)ks * 256u);
#pragma unroll
            for (int mi = 0; mi < 4; ++mi)
#pragma unroll
                for (int i = 0; i < 2; ++i) {
                    mma16816(acc[mi][2 * i],     a[mi], &b[i][0]);
                    mma16816(acc[mi][2 * i + 1], a[mi], &b[i][2]);
                }
        }
    };

    // ---- 3-stage pipeline ----
    stage(0); CP_COMMIT();
    stage(1); CP_COMMIT();

    for (int c = 0; c < NCHUNK; ++c) {
        if (c + 1 < NCHUNK) { CP_WAIT1(); } else { CP_WAIT0(); }
        __syncthreads();
        if (c + 2 < NCHUNK) { stage(c + 2); CP_COMMIT(); }
        compute(c);
        __syncthreads();
    }

    // ---- epilogue: relu(h + b1) . W2 + b2, quad-reduce over d ----
    const int gid = lane >> 2;
    const int tq  = lane & 3;
#pragma unroll
    for (int ni = 0; ni < 4; ++ni) {
        const int l = l0 + wn * 4 + ni;
        float2 bbv = *reinterpret_cast<const float2*>(b1 + (size_t)l * 8 + tq * 2);
        float2 wwv = *reinterpret_cast<const float2*>(W2 + (size_t)l * 8 + tq * 2);
        const float b2v = __ldg(b2 + l);
#pragma unroll
        for (int mi = 0; mi < 4; ++mi) {
            float s0 = fmaxf(acc[mi][ni][0] + bbv.x, 0.0f) * wwv.x
                     + fmaxf(acc[mi][ni][1] + bbv.y, 0.0f) * wwv.y;
            float s1 = fmaxf(acc[mi][ni][2] + bbv.x, 0.0f) * wwv.x
                     + fmaxf(acc[mi][ni][3] + bbv.y, 0.0f) * wwv.y;
            s0 += __shfl_xor_sync(0xffffffffu, s0, 1);
            s0 += __shfl_xor_sync(0xffffffffu, s0, 2);
            s1 += __shfl_xor_sync(0xffffffffu, s1, 1);
            s1 += __shfl_xor_sync(0xffffffffu, s1, 2);
            if (tq == 0) {
                const int b = m0 + wm * 64 + mi * 16 + gid;
                out[(size_t)b * L + l]       = s0 + b2v;
                out[(size_t)(b + 8) * L + l] = s1 + b2v;
            }
        }
    }
}

extern "C" void kernel_launch(void* const* d_in, const int* in_sizes, int n_in,
                              void* d_out, int out_size)
{
    const float* emb = (const float*)d_in[0];  // [B, H]
    const float* W1  = (const float*)d_in[1];  // [L, H, 8]
    const float* b1  = (const float*)d_in[2];  // [L, 8]
    const float* W2  = (const float*)d_in[3];  // [L, 8]
    const float* b2  = (const float*)d_in[4];  // [L]
    float* out       = (float*)d_out;          // [B, L]

    cudaFuncSetAttribute(imec_hmma_kernel,
                         cudaFuncAttributeMaxDynamicSharedMemorySize, SMEM_DYN);

    cvt_emb_kernel<<<BB * H / 4 / 256, 256>>>(emb);
    cvt_w1_kernel<<<40000, 256>>>(W1);   // 10,240,000 uint4 outputs
    imec_hmma_kernel<<<(L / LPB) * 2, 256, SMEM_DYN>>>(b1, W2, b2, out);
}

// round 9
// speedup vs baseline: 8.6644x; 1.3360x over previous
#include <cuda_runtime.h>
#include <cuda_fp16.h>
#include <cstdint>

// Problem constants
constexpr int BB = 256;     // batch = M per CTA (full batch)
constexpr int H  = 1024;    // hidden
constexpr int L  = 10000;   // labels
constexpr int LPB = 16;     // labels per CTA (N = 128)
constexpr int KC = 64;      // K per chunk
constexpr int NCHUNK = H / KC;  // 16
constexpr int NSTAGE_A = 3;

// smem: A 3 stages x 32KB, then B 2 bufs x 16KB
constexpr int OFF_A = 0;
constexpr int A_STAGE = 32768;
constexpr int OFF_B = NSTAGE_A * A_STAGE;        // 98304
constexpr int B_BUF = 16384;
constexpr int SMEM_DYN = 1024 + OFF_B + 2 * B_BUF;   // 132096

// pre-converted fp16 embeddings [256][1024]
__device__ __align__(16) __half g_eA[BB * H];

// ---------------- helpers ----------------
__device__ __forceinline__ uint32_t smem_u32(const void* p) {
    uint32_t a;
    asm("{ .reg .u64 t; cvta.to.shared.u64 t, %1; cvt.u32.u64 %0, t; }" : "=r"(a) : "l"(p));
    return a;
}
__device__ __forceinline__ void cpasync16(uint32_t dst, const void* src) {
    asm volatile("cp.async.cg.shared.global [%0], [%1], 16;" :: "r"(dst), "l"(src));
}
#define CP_COMMIT() asm volatile("cp.async.commit_group;" ::: "memory")
#define CP_WAIT1()  asm volatile("cp.async.wait_group 1;" ::: "memory")
#define CP_WAIT0()  asm volatile("cp.async.wait_group 0;" ::: "memory")

__device__ __forceinline__ void ldsm4(uint32_t* r, uint32_t addr) {
    asm volatile("ldmatrix.sync.aligned.m8n8.x4.shared.b16 {%0,%1,%2,%3}, [%4];"
                 : "=r"(r[0]), "=r"(r[1]), "=r"(r[2]), "=r"(r[3]) : "r"(addr));
}
__device__ __forceinline__ void ldsm4t(uint32_t* r, uint32_t addr) {
    asm volatile("ldmatrix.sync.aligned.m8n8.x4.trans.shared.b16 {%0,%1,%2,%3}, [%4];"
                 : "=r"(r[0]), "=r"(r[1]), "=r"(r[2]), "=r"(r[3]) : "r"(addr));
}
__device__ __forceinline__ void mma16816(float* c, const uint32_t* a, const uint32_t* b) {
    asm volatile(
        "mma.sync.aligned.m16n8k16.row.col.f32.f16.f16.f32 "
        "{%0,%1,%2,%3}, {%4,%5,%6,%7}, {%8,%9}, {%0,%1,%2,%3};"
        : "+f"(c[0]), "+f"(c[1]), "+f"(c[2]), "+f"(c[3])
        : "r"(a[0]), "r"(a[1]), "r"(a[2]), "r"(a[3]), "r"(b[0]), "r"(b[1]));
}
__device__ __forceinline__ uint32_t pkh2(float x0, float x1) {
    __half2 h = __float22half2_rn(make_float2(x0, x1));
    return *reinterpret_cast<uint32_t*>(&h);
}

// ---------------- pre-kernel: emb fp32 -> fp16 ----------------
__global__ void cvt_emb_kernel(const float* __restrict__ emb) {
    int i = blockIdx.x * blockDim.x + threadIdx.x;   // 65536 float4s
    float4 v = reinterpret_cast<const float4*>(emb)[i];
    reinterpret_cast<uint2*>(g_eA)[i] = make_uint2(pkh2(v.x, v.y), pkh2(v.z, v.w));
}

// ---------------- main kernel ----------------
__global__ __launch_bounds__(512, 1)
void imec_hmma_kernel(const float* __restrict__ W1,
                      const float* __restrict__ b1,
                      const float* __restrict__ W2,
                      const float* __restrict__ b2,
                      float* __restrict__ out)
{
    extern __shared__ char smraw[];
    uint32_t sraw = smem_u32(smraw);
    uint32_t sb = (sraw + 1023u) & ~1023u;
    char* smc = smraw + (sb - sraw);

    const int tid  = threadIdx.x;
    const int lane = tid & 31;
    const int wid  = tid >> 5;        // 0..15
    const int wm   = wid & 3;         // warp M group: 64 rows each (4x64=256)
    const int wn   = wid >> 2;        // warp N group: 32 cols = 4 labels (4x32=128)

    const int l0 = blockIdx.x * LPB;

    // ---- A staging: thread -> (row, k-half), 128B swizzled rows ----
    const int ar = tid >> 1;          // 0..255
    const int ahalf = tid & 1;
    const char* aSrc = reinterpret_cast<const char*>(g_eA)
                     + (size_t)ar * (H * 2) + ahalf * 64;
    const uint32_t aDstBase = (uint32_t)(ar * 128);
    const uint32_t arx = (uint32_t)(ar & 7);

    // ---- B staging: warp = label; lane j-th LDG.128 at base + j*512 + lane*16 ----
    // float idx = j*128 + lane*4  ->  k-row = j*16 + (lane>>1), d-half = lane&1
    const float* bSrc = W1 + (size_t)(l0 + wid) * (H * 8);
    const uint32_t bDstBase = (uint32_t)(wid * 1024) + (uint32_t)(lane * 8);
    // fp16 dst offset within blob for load j: j*256 + lane*8  (contiguous per warp)

    // ---- A fragment addresses (K-major, swizzled) ----
    uint32_t aOff[4], aXor[4];
#pragma unroll
    for (int mi = 0; mi < 4; ++mi) {
        int r = wm * 64 + mi * 16 + (lane & 15);
        aOff[mi] = (uint32_t)r * 128u;
        aXor[mi] = (uint32_t)(r & 7) << 4;
    }
    const uint32_t aKadd = (uint32_t)(lane >> 4) << 4;

    // ---- B fragment addresses (per-label 1KB MN-major blobs, trans ldsm) ----
    uint32_t bOff[2];
#pragma unroll
    for (int i = 0; i < 2; ++i)
        bOff[i] = (uint32_t)((wn * 4 + 2 * i + (lane >> 4)) * 1024 + (lane & 15) * 16);

    float acc[4][4][4];
#pragma unroll
    for (int mi = 0; mi < 4; ++mi)
#pragma unroll
        for (int ni = 0; ni < 4; ++ni)
#pragma unroll
            for (int k = 0; k < 4; ++k) acc[mi][ni][k] = 0.0f;

    float4 bv[4];   // W1 prefetch: 4 coalesced LDG.128

    auto stageA = [&](int c) {
        const int p = c % NSTAGE_A;
        const uint32_t ad = sb + (uint32_t)(OFF_A + p * A_STAGE) + aDstBase;
        const char* as = aSrc + c * 128;
#pragma unroll
        for (int j = 0; j < 4; ++j) {
            uint32_t u = (uint32_t)(ahalf * 4 + j);
            cpasync16(ad + ((u ^ arx) << 4), as + j * 16);
        }
    };

    auto ldgB = [&](int c) {
        const float* s = bSrc + (size_t)c * (KC * 8);
#pragma unroll
        for (int j = 0; j < 4; ++j)
            bv[j] = *reinterpret_cast<const float4*>(s + j * 128 + lane * 4);
    };

    auto stsB = [&](int c) {
        const int p = c & 1;
        char* bd = smc + OFF_B + p * B_BUF + bDstBase;
#pragma unroll
        for (int j = 0; j < 4; ++j) {
            uint2 w = make_uint2(pkh2(bv[j].x, bv[j].y), pkh2(bv[j].z, bv[j].w));
            *reinterpret_cast<uint2*>(bd + j * 256) = w;
        }
    };

    auto compute = [&](int c) {
        const uint32_t bA = sb + (uint32_t)(OFF_A + (c % NSTAGE_A) * A_STAGE);
        const uint32_t bB = sb + (uint32_t)(OFF_B + (c & 1) * B_BUF);
#pragma unroll
        for (int ks = 0; ks < 4; ++ks) {
            const uint32_t koff = (uint32_t)ks * 32u;
            uint32_t a[4][4], b[2][4];
#pragma unroll
            for (int mi = 0; mi < 4; ++mi)
                ldsm4(a[mi], bA + aOff[mi] + ((koff + aKadd) ^ aXor[mi]));
#pragma unroll
            for (int i = 0; i < 2; ++i)
                ldsm4t(b[i], bB + bOff[i] + (uint32_t)ks * 256u);
#pragma unroll
            for (int mi = 0; mi < 4; ++mi)
#pragma unroll
                for (int i = 0; i < 2; ++i) {
                    mma16816(acc[mi][2 * i],     a[mi], &b[i][0]);
                    mma16816(acc[mi][2 * i + 1], a[mi], &b[i][2]);
                }
        }
    };

    // ---- pipeline prologue ----
    stageA(0); CP_COMMIT();
    stageA(1); CP_COMMIT();
    ldgB(0);
    stsB(0);
    CP_WAIT1();        // A(0) ready
    __syncthreads();

    // ---- main loop ----
    for (int c = 0; c < NCHUNK; ++c) {
        if (c + 1 < NCHUNK) ldgB(c + 1);      // coalesced LDG, hidden under MMA
        compute(c);
        if (c + 1 < NCHUNK) stsB(c + 1);
        if (c + 2 < NCHUNK) { stageA(c + 2); CP_COMMIT(); }
        if (c + 1 < NCHUNK) {
            if (c + 2 < NCHUNK) { CP_WAIT1(); } else { CP_WAIT0(); }
        }
        __syncthreads();
    }

    // ---- epilogue: relu(h + b1) . W2 + b2, quad-reduce over d ----
    const int gid = lane >> 2;
    const int tq  = lane & 3;
#pragma unroll
    for (int ni = 0; ni < 4; ++ni) {
        const int l = l0 + wn * 4 + ni;
        float2 bbv = *reinterpret_cast<const float2*>(b1 + (size_t)l * 8 + tq * 2);
        float2 wwv = *reinterpret_cast<const float2*>(W2 + (size_t)l * 8 + tq * 2);
        const float b2v = __ldg(b2 + l);
#pragma unroll
        for (int mi = 0; mi < 4; ++mi) {
            float s0 = fmaxf(acc[mi][ni][0] + bbv.x, 0.0f) * wwv.x
                     + fmaxf(acc[mi][ni][1] + bbv.y, 0.0f) * wwv.y;
            float s1 = fmaxf(acc[mi][ni][2] + bbv.x, 0.0f) * wwv.x
                     + fmaxf(acc[mi][ni][3] + bbv.y, 0.0f) * wwv.y;
            s0 += __shfl_xor_sync(0xffffffffu, s0, 1);
            s0 += __shfl_xor_sync(0xffffffffu, s0, 2);
            s1 += __shfl_xor_sync(0xffffffffu, s1, 1);
            s1 += __shfl_xor_sync(0xffffffffu, s1, 2);
            if (tq == 0) {
                const int b = wm * 64 + mi * 16 + gid;
                out[(size_t)b * L + l]       = s0 + b2v;
                out[(size_t)(b + 8) * L + l] = s1 + b2v;
            }
        }
    }
}

extern "C" void kernel_launch(void* const* d_in, const int* in_sizes, int n_in,
                              void* d_out, int out_size)
{
    const float* emb = (const float*)d_in[0];  // [B, H]
    const float* W1  = (const float*)d_in[1];  // [L, H, 8]
    const float* b1  = (const float*)d_in[2];  // [L, 8]
    const float* W2  = (const float*)d_in[3];  // [L, 8]
    const float* b2  = (const float*)d_in[4];  // [L]
    float* out       = (float*)d_out;          // [B, L]

    cudaFuncSetAttribute(imec_hmma_kernel,
                         cudaFuncAttributeMaxDynamicSharedMemorySize, SMEM_DYN);

    cvt_emb_kernel<<<BB * H / 4 / 256, 256>>>(emb);
    imec_hmma_kernel<<<L / LPB, 512, SMEM_DYN>>>(W1, b1, W2, b2, out);
}